// round 1
// baseline (speedup 1.0000x reference)
#include <cuda_runtime.h>

#define THREADS 256
#define RROWS   32
#define SP64    68   // padded stride for 64-wide rows (avoids bank-aligned row stride)
#define SP32    36   // padded stride for 32-wide rows

// shared memory footprint in floats
#define NF_SMEM (RROWS*SP64*2 + RROWS*SP32*2 + 5*RROWS*SP64 \
                 + 64*32 + 32*32 + 32*64 + 64*64 + 64*64 + 32 + 32 + 64 + 64 + 64)

__device__ __forceinline__ float fast_tanh(float x) {
    // tanh(x) = 1 - 2/(exp(2x)+1); abs err ~1e-7, saturates correctly at +-inf
    float e = __expf(2.0f * x);
    return 1.0f - __fdividef(2.0f, e + 1.0f);
}

#define F4MAD(acc, c, v) do { \
    (acc).x = fmaf((c), (v).x, (acc).x); \
    (acc).y = fmaf((c), (v).y, (acc).y); \
    (acc).z = fmaf((c), (v).z, (acc).z); \
    (acc).w = fmaf((c), (v).w, (acc).w); } while (0)

// N=32 layer with tanh: out[r][g4..g4+3] = tanh(bias + sum_k in[r][k]*Wt[k][o])
// Wt laid out k-major: Wt[k*32 + o]. in stride = strideIn, out stride = SP32.
template<int K>
__device__ __forceinline__ void layerN32(const float* __restrict__ in, int strideIn,
                                         const float* __restrict__ Wt,
                                         const float* __restrict__ bias,
                                         float* __restrict__ out, int tid)
{
    const int r  = tid >> 3;
    const int g4 = (tid & 7) << 2;
    float a0 = bias[g4 + 0], a1 = bias[g4 + 1], a2 = bias[g4 + 2], a3 = bias[g4 + 3];
    const float* yrow = in + r * strideIn;
    #pragma unroll 2
    for (int k = 0; k < K; k += 4) {
        float4 yv = *(const float4*)(yrow + k);
        float yk[4] = {yv.x, yv.y, yv.z, yv.w};
        #pragma unroll
        for (int kk = 0; kk < 4; kk++) {
            float4 wv = *(const float4*)(Wt + (k + kk) * 32 + g4);
            a0 = fmaf(yk[kk], wv.x, a0);
            a1 = fmaf(yk[kk], wv.y, a1);
            a2 = fmaf(yk[kk], wv.z, a2);
            a3 = fmaf(yk[kk], wv.w, a3);
        }
    }
    float* o = out + r * SP32 + g4;
    o[0] = fast_tanh(a0); o[1] = fast_tanh(a1);
    o[2] = fast_tanh(a2); o[3] = fast_tanh(a3);
}

// N=64 linear layer (no activation): out[r][{g4, 32+g4}+j]. Wt k-major: Wt[k*64 + o].
template<int K>
__device__ __forceinline__ void layerN64(const float* __restrict__ in, int strideIn,
                                         const float* __restrict__ Wt,
                                         const float* __restrict__ bias,
                                         float* __restrict__ out, int tid)
{
    const int r  = tid >> 3;
    const int g4 = (tid & 7) << 2;
    float a[8];
    {
        float4 b0 = *(const float4*)(bias + g4);
        float4 b1 = *(const float4*)(bias + 32 + g4);
        a[0] = b0.x; a[1] = b0.y; a[2] = b0.z; a[3] = b0.w;
        a[4] = b1.x; a[5] = b1.y; a[6] = b1.z; a[7] = b1.w;
    }
    const float* yrow = in + r * strideIn;
    #pragma unroll 2
    for (int k = 0; k < K; k += 4) {
        float4 yv = *(const float4*)(yrow + k);
        float yk[4] = {yv.x, yv.y, yv.z, yv.w};
        #pragma unroll
        for (int kk = 0; kk < 4; kk++) {
            float4 w0 = *(const float4*)(Wt + (k + kk) * 64 + g4);
            float4 w1 = *(const float4*)(Wt + (k + kk) * 64 + 32 + g4);
            a[0] = fmaf(yk[kk], w0.x, a[0]); a[1] = fmaf(yk[kk], w0.y, a[1]);
            a[2] = fmaf(yk[kk], w0.z, a[2]); a[3] = fmaf(yk[kk], w0.w, a[3]);
            a[4] = fmaf(yk[kk], w1.x, a[4]); a[5] = fmaf(yk[kk], w1.y, a[5]);
            a[6] = fmaf(yk[kk], w1.z, a[6]); a[7] = fmaf(yk[kk], w1.w, a[7]);
        }
    }
    float* o = out + r * SP64;
    *(float4*)(o + g4)      = make_float4(a[0], a[1], a[2], a[3]);
    *(float4*)(o + 32 + g4) = make_float4(a[4], a[5], a[6], a[7]);
}

// decode: ys[row0+r, t, :] = sZ[r,:] @ decW^T + decb   (K=64, N=64, write to global)
__device__ __forceinline__ void decode_store(const float* __restrict__ sZ,
                                             const float* __restrict__ Dt,
                                             const float* __restrict__ db,
                                             float* __restrict__ ys,
                                             int row0, int T, int t, int tid)
{
    const int r  = tid >> 3;
    const int g4 = (tid & 7) << 2;
    float a[8];
    {
        float4 b0 = *(const float4*)(db + g4);
        float4 b1 = *(const float4*)(db + 32 + g4);
        a[0] = b0.x; a[1] = b0.y; a[2] = b0.z; a[3] = b0.w;
        a[4] = b1.x; a[5] = b1.y; a[6] = b1.z; a[7] = b1.w;
    }
    const float* yrow = sZ + r * SP64;
    #pragma unroll 2
    for (int k = 0; k < 64; k += 4) {
        float4 yv = *(const float4*)(yrow + k);
        float yk[4] = {yv.x, yv.y, yv.z, yv.w};
        #pragma unroll
        for (int kk = 0; kk < 4; kk++) {
            float4 w0 = *(const float4*)(Dt + (k + kk) * 64 + g4);
            float4 w1 = *(const float4*)(Dt + (k + kk) * 64 + 32 + g4);
            a[0] = fmaf(yk[kk], w0.x, a[0]); a[1] = fmaf(yk[kk], w0.y, a[1]);
            a[2] = fmaf(yk[kk], w0.z, a[2]); a[3] = fmaf(yk[kk], w0.w, a[3]);
            a[4] = fmaf(yk[kk], w1.x, a[4]); a[5] = fmaf(yk[kk], w1.y, a[5]);
            a[6] = fmaf(yk[kk], w1.z, a[6]); a[7] = fmaf(yk[kk], w1.w, a[7]);
        }
    }
    float* dst = ys + ((size_t)(row0 + r) * T + t) * 64;
    *(float4*)(dst + g4)      = make_float4(a[0], a[1], a[2], a[3]);
    *(float4*)(dst + 32 + g4) = make_float4(a[4], a[5], a[6], a[7]);
}

__global__ void __launch_bounds__(THREADS, 1)
ode_kernel(const float* __restrict__ ts,   const float* __restrict__ y0,
           const float* __restrict__ encW, const float* __restrict__ encb,
           const float* __restrict__ W1,   const float* __restrict__ b1,
           const float* __restrict__ W2,   const float* __restrict__ b2,
           const float* __restrict__ W3,   const float* __restrict__ b3,
           const float* __restrict__ decW, const float* __restrict__ decb,
           float* __restrict__ ys, float* __restrict__ zs, int T, int B)
{
    extern __shared__ float sm[];
    float* sZ   = sm;                       // [RROWS][SP64]
    float* sY   = sZ  + RROWS * SP64;       // [RROWS][SP64] stage input / k6
    float* sH1  = sY  + RROWS * SP64;       // [RROWS][SP32]
    float* sH2  = sH1 + RROWS * SP32;       // [RROWS][SP32]
    float* sKa  = sH2 + RROWS * SP32;       // 5 x [RROWS][SP64]  (k1..k5)
    float* sW1t = sKa + 5 * RROWS * SP64;   // [64][32]
    float* sW2t = sW1t + 64 * 32;           // [32][32]
    float* sW3t = sW2t + 32 * 32;           // [32][64]
    float* sEt  = sW3t + 32 * 64;           // [64][64] encW^T
    float* sDt  = sEt  + 64 * 64;           // [64][64] decW^T
    float* sb1_ = sDt  + 64 * 64;           // [32]
    float* sb2_ = sb1_ + 32;                // [32]
    float* sb3_ = sb2_ + 32;                // [64]
    float* sEb  = sb3_ + 64;                // [64]
    float* sDb  = sEb  + 64;                // [64]

    const int tid  = threadIdx.x;
    const int row0 = blockIdx.x * RROWS;

    // ---- stage weights into shared, transposed to k-major ----
    for (int i = tid; i < 32 * 64; i += THREADS) { int o = i >> 6, k = i & 63; sW1t[k * 32 + o] = W1[i]; }
    for (int i = tid; i < 32 * 32; i += THREADS) { int o = i >> 5, k = i & 31; sW2t[k * 32 + o] = W2[i]; }
    for (int i = tid; i < 64 * 32; i += THREADS) { int o = i >> 5, k = i & 31; sW3t[k * 64 + o] = W3[i]; }
    for (int i = tid; i < 64 * 64; i += THREADS) { int o = i >> 6, k = i & 63; sEt[k * 64 + o] = encW[i]; }
    for (int i = tid; i < 64 * 64; i += THREADS) { int o = i >> 6, k = i & 63; sDt[k * 64 + o] = decW[i]; }
    if (tid < 32) { sb1_[tid] = b1[tid]; sb2_[tid] = b2[tid]; }
    if (tid < 64) { sb3_[tid] = b3[tid]; sEb[tid] = encb[tid]; sDb[tid] = decb[tid]; }

    // ---- stage y0 rows into sY ----
    for (int i = tid; i < RROWS * 16; i += THREADS) {
        int r = i >> 4, c = (i & 15) << 2;
        *(float4*)&sY[r * SP64 + c] = *(const float4*)&y0[(size_t)(row0 + r) * 64 + c];
    }
    __syncthreads();

    const float dt = (ts[T - 1] - ts[0]) / (float)(T - 1);

    // Tsit5 coefficients, pre-scaled by dt
    const float c21 = dt * 0.161f;
    const float c31 = dt * -0.008480655492356989f, c32 = dt * 0.335480655492357f;
    const float c41 = dt * 2.8971530571054935f,    c42 = dt * -6.359448489975075f,
                c43 = dt * 4.3622954328695815f;
    const float c51 = dt * 5.325864828439257f,     c52 = dt * -11.748883564062828f,
                c53 = dt * 7.4955393428898365f,    c54 = dt * -0.09249506636175525f;
    const float c61 = dt * 5.86145544294642f,      c62 = dt * -12.92096931784711f,
                c63 = dt * 8.159367898576159f,     c64 = dt * -0.071584973281401f,
                c65 = dt * -0.028269050394068383f;
    const float d1 = dt * 0.09646076681806523f, d2 = dt * 0.01f,
                d3 = dt * 0.4798896504144996f,  d4 = dt * 1.379008574103742f,
                d5 = dt * -3.290069515436081f,  d6 = dt * 2.324710524099774f;

    // ---- encoder: z0 = y0 @ encW^T + encb ----
    layerN64<64>(sY, SP64, sEt, sEb, sZ, tid);
    __syncthreads();

    // ---- emit t = 0 ----
    for (int i = tid; i < RROWS * 16; i += THREADS) {
        int r = i >> 4, c = (i & 15) << 2;
        *(float4*)&zs[((size_t)(row0 + r) * T) * 64 + c] = *(const float4*)&sZ[r * SP64 + c];
    }
    decode_store(sZ, sDt, sDb, ys, row0, T, 0, tid);

    float* sK1 = sKa + 0 * RROWS * SP64;
    float* sK2 = sKa + 1 * RROWS * SP64;
    float* sK3 = sKa + 2 * RROWS * SP64;
    float* sK4 = sKa + 3 * RROWS * SP64;
    float* sK5 = sKa + 4 * RROWS * SP64;

    #pragma unroll 1
    for (int t = 1; t < T; t++) {
        // ---- stage 1: k1 = f(z) ----
        layerN32<64>(sZ, SP64, sW1t, sb1_, sH1, tid);  __syncthreads();
        layerN32<32>(sH1, SP32, sW2t, sb2_, sH2, tid); __syncthreads();
        layerN64<32>(sH2, SP32, sW3t, sb3_, sK1, tid); __syncthreads();

        // ---- stage 2 ----
        for (int i = tid; i < RROWS * 16; i += THREADS) {
            int r = i >> 4, off = r * SP64 + ((i & 15) << 2);
            float4 y  = *(const float4*)&sZ[off];
            float4 k1 = *(const float4*)&sK1[off];
            F4MAD(y, c21, k1);
            *(float4*)&sY[off] = y;
        }
        __syncthreads();
        layerN32<64>(sY, SP64, sW1t, sb1_, sH1, tid);  __syncthreads();
        layerN32<32>(sH1, SP32, sW2t, sb2_, sH2, tid); __syncthreads();
        layerN64<32>(sH2, SP32, sW3t, sb3_, sK2, tid); __syncthreads();

        // ---- stage 3 ----
        for (int i = tid; i < RROWS * 16; i += THREADS) {
            int r = i >> 4, off = r * SP64 + ((i & 15) << 2);
            float4 y  = *(const float4*)&sZ[off];
            float4 k1 = *(const float4*)&sK1[off];
            float4 k2 = *(const float4*)&sK2[off];
            F4MAD(y, c31, k1); F4MAD(y, c32, k2);
            *(float4*)&sY[off] = y;
        }
        __syncthreads();
        layerN32<64>(sY, SP64, sW1t, sb1_, sH1, tid);  __syncthreads();
        layerN32<32>(sH1, SP32, sW2t, sb2_, sH2, tid); __syncthreads();
        layerN64<32>(sH2, SP32, sW3t, sb3_, sK3, tid); __syncthreads();

        // ---- stage 4 ----
        for (int i = tid; i < RROWS * 16; i += THREADS) {
            int r = i >> 4, off = r * SP64 + ((i & 15) << 2);
            float4 y  = *(const float4*)&sZ[off];
            float4 k1 = *(const float4*)&sK1[off];
            float4 k2 = *(const float4*)&sK2[off];
            float4 k3 = *(const float4*)&sK3[off];
            F4MAD(y, c41, k1); F4MAD(y, c42, k2); F4MAD(y, c43, k3);
            *(float4*)&sY[off] = y;
        }
        __syncthreads();
        layerN32<64>(sY, SP64, sW1t, sb1_, sH1, tid);  __syncthreads();
        layerN32<32>(sH1, SP32, sW2t, sb2_, sH2, tid); __syncthreads();
        layerN64<32>(sH2, SP32, sW3t, sb3_, sK4, tid); __syncthreads();

        // ---- stage 5 ----
        for (int i = tid; i < RROWS * 16; i += THREADS) {
            int r = i >> 4, off = r * SP64 + ((i & 15) << 2);
            float4 y  = *(const float4*)&sZ[off];
            float4 k1 = *(const float4*)&sK1[off];
            float4 k2 = *(const float4*)&sK2[off];
            float4 k3 = *(const float4*)&sK3[off];
            float4 k4 = *(const float4*)&sK4[off];
            F4MAD(y, c51, k1); F4MAD(y, c52, k2); F4MAD(y, c53, k3); F4MAD(y, c54, k4);
            *(float4*)&sY[off] = y;
        }
        __syncthreads();
        layerN32<64>(sY, SP64, sW1t, sb1_, sH1, tid);  __syncthreads();
        layerN32<32>(sH1, SP32, sW2t, sb2_, sH2, tid); __syncthreads();
        layerN64<32>(sH2, SP32, sW3t, sb3_, sK5, tid); __syncthreads();

        // ---- stage 6 (k6 goes into sY; sY's stage input already consumed by L1) ----
        for (int i = tid; i < RROWS * 16; i += THREADS) {
            int r = i >> 4, off = r * SP64 + ((i & 15) << 2);
            float4 y  = *(const float4*)&sZ[off];
            float4 k1 = *(const float4*)&sK1[off];
            float4 k2 = *(const float4*)&sK2[off];
            float4 k3 = *(const float4*)&sK3[off];
            float4 k4 = *(const float4*)&sK4[off];
            float4 k5 = *(const float4*)&sK5[off];
            F4MAD(y, c61, k1); F4MAD(y, c62, k2); F4MAD(y, c63, k3);
            F4MAD(y, c64, k4); F4MAD(y, c65, k5);
            *(float4*)&sY[off] = y;
        }
        __syncthreads();
        layerN32<64>(sY, SP64, sW1t, sb1_, sH1, tid);  __syncthreads();
        layerN32<32>(sH1, SP32, sW2t, sb2_, sH2, tid); __syncthreads();
        layerN64<32>(sH2, SP32, sW3t, sb3_, sY, tid);  __syncthreads();  // k6 -> sY

        // ---- combine + emit zs[t] ----
        for (int i = tid; i < RROWS * 16; i += THREADS) {
            int r = i >> 4, c = (i & 15) << 2;
            int off = r * SP64 + c;
            float4 z  = *(const float4*)&sZ[off];
            float4 k1 = *(const float4*)&sK1[off];
            float4 k2 = *(const float4*)&sK2[off];
            float4 k3 = *(const float4*)&sK3[off];
            float4 k4 = *(const float4*)&sK4[off];
            float4 k5 = *(const float4*)&sK5[off];
            float4 k6 = *(const float4*)&sY[off];
            F4MAD(z, d1, k1); F4MAD(z, d2, k2); F4MAD(z, d3, k3);
            F4MAD(z, d4, k4); F4MAD(z, d5, k5); F4MAD(z, d6, k6);
            *(float4*)&sZ[off] = z;
            *(float4*)&zs[((size_t)(row0 + r) * T + t) * 64 + c] = z;
        }
        __syncthreads();

        // ---- decoder for this t (reads sZ, writes global only; no sync needed after) ----
        decode_store(sZ, sDt, sDb, ys, row0, T, t, tid);
    }
}

extern "C" void kernel_launch(void* const* d_in, const int* in_sizes, int n_in,
                              void* d_out, int out_size)
{
    const float* ts   = (const float*)d_in[0];
    const float* y0   = (const float*)d_in[1];
    const float* encW = (const float*)d_in[2];
    const float* encb = (const float*)d_in[3];
    const float* W1   = (const float*)d_in[4];
    const float* b1   = (const float*)d_in[5];
    const float* W2   = (const float*)d_in[6];
    const float* b2   = (const float*)d_in[7];
    const float* W3   = (const float*)d_in[8];
    const float* b3   = (const float*)d_in[9];
    const float* decW = (const float*)d_in[10];
    const float* decb = (const float*)d_in[11];

    const int T = in_sizes[0];         // 101
    const int B = in_sizes[1] / 64;    // 4096

    float* ys = (float*)d_out;                      // [B, T, 64]
    float* zs = ys + (size_t)B * T * 64;            // [B, T, 64]

    const size_t smem_bytes = (size_t)NF_SMEM * sizeof(float);  // ~124 KB
    cudaFuncSetAttribute(ode_kernel, cudaFuncAttributeMaxDynamicSharedMemorySize,
                         (int)smem_bytes);

    const int blocks = (B + RROWS - 1) / RROWS;     // 128
    ode_kernel<<<blocks, THREADS, smem_bytes>>>(ts, y0, encW, encb, W1, b1, W2, b2,
                                                W3, b3, decW, decb, ys, zs, T, B);
}

// round 7
// speedup vs baseline: 1.0706x; 1.0706x over previous
#include <cuda_runtime.h>

#define THREADS 224
#define RROWS   28
#define SP64    68            // padded row stride (floats), 16B-aligned rows
#define SP32    36
#define KSTRIDE (RROWS*SP64)

// floats: 7 act64 bufs + 2 act32 bufs + packed weights + biases + 31 u64 consts
#define NF_SMEM (7*RROWS*SP64 + 2*RROWS*SP32 + 2048+1024+2048+4096+4096 \
                 + 32+32+64+64+64 + 62)

typedef unsigned long long u64;

// Tsit5 tableau (stage-combine rows s=1..5, 5 coeffs each; and 5th-order weights)
__constant__ float TSIT_C[25] = {
    0.161f, 0.f, 0.f, 0.f, 0.f,
    -0.008480655492356989f, 0.335480655492357f, 0.f, 0.f, 0.f,
    2.8971530571054935f, -6.359448489975075f, 4.3622954328695815f, 0.f, 0.f,
    5.325864828439257f, -11.748883564062828f, 7.4955393428898365f, -0.09249506636175525f, 0.f,
    5.86145544294642f, -12.92096931784711f, 8.159367898576159f, -0.071584973281401f, -0.028269050394068383f
};
__constant__ float TSIT_B[6] = {
    0.09646076681806523f, 0.01f, 0.4798896504144996f,
    1.379008574103742f, -3.290069515436081f, 2.324710524099774f
};

__device__ __forceinline__ void ffma2(u64 &d, u64 a, u64 b) {
    asm("fma.rn.f32x2 %0, %1, %2, %0;" : "+l"(d) : "l"(a), "l"(b));
}
__device__ __forceinline__ float hadd2(u64 a) {
    float lo, hi;
    asm("mov.b64 {%0,%1}, %2;" : "=f"(lo), "=f"(hi) : "l"(a));
    return lo + hi;
}
__device__ __forceinline__ u64 splat2(float c) {
    u64 d; asm("mov.b64 %0, {%1,%1};" : "=l"(d) : "f"(c)); return d;
}
__device__ __forceinline__ float fast_tanh(float x) {
    float e = __expf(2.0f * x);
    return 1.0f - __fdividef(2.0f, e + 1.0f);
}

// ---- N=32 tanh layer, packed over k-pairs. Wp rows: [K/2][64] (pair(o) at 2o). ----
template<int K>
__device__ __forceinline__ void layerN32p(const float* __restrict__ in, int sIn,
        const float* __restrict__ Wp, const float* __restrict__ bias,
        float* __restrict__ out, int r, int g4)
{
    u64 a0 = 0, a1 = 0, a2 = 0, a3 = 0;
    const float* yrow = in + r * sIn;
    const float* wb = Wp + 2 * g4;
    #pragma unroll
    for (int q = 0; q < K / 4; q++) {
        ulonglong2 yv = *(const ulonglong2*)(yrow + 4 * q);
        ulonglong2 wa = *(const ulonglong2*)(wb + 128 * q);
        ulonglong2 wc = *(const ulonglong2*)(wb + 128 * q + 4);
        ffma2(a0, yv.x, wa.x); ffma2(a1, yv.x, wa.y);
        ffma2(a2, yv.x, wc.x); ffma2(a3, yv.x, wc.y);
        ulonglong2 we = *(const ulonglong2*)(wb + 128 * q + 64);
        ulonglong2 wg = *(const ulonglong2*)(wb + 128 * q + 68);
        ffma2(a0, yv.y, we.x); ffma2(a1, yv.y, we.y);
        ffma2(a2, yv.y, wg.x); ffma2(a3, yv.y, wg.y);
    }
    float* o = out + r * SP32 + g4;
    o[0] = fast_tanh(hadd2(a0) + bias[g4 + 0]);
    o[1] = fast_tanh(hadd2(a1) + bias[g4 + 1]);
    o[2] = fast_tanh(hadd2(a2) + bias[g4 + 2]);
    o[3] = fast_tanh(hadd2(a3) + bias[g4 + 3]);
}

// ---- N=64 GEMM core, packed. Wp rows: [K/2][128]. 8 outputs: g4..g4+3, 32+g4.. ----
template<int K>
__device__ __forceinline__ void gemm64acc(const float* __restrict__ yrow,
        const float* __restrict__ Wp, int g4, u64* __restrict__ a)
{
    const float* wb  = Wp + 2 * g4;
    const float* wb2 = Wp + 64 + 2 * g4;
    #pragma unroll
    for (int q = 0; q < K / 4; q++) {
        ulonglong2 yv = *(const ulonglong2*)(yrow + 4 * q);
        const int row0 = 256 * q;
        ulonglong2 w0 = *(const ulonglong2*)(wb  + row0);
        ulonglong2 w1 = *(const ulonglong2*)(wb  + row0 + 4);
        ulonglong2 w2 = *(const ulonglong2*)(wb2 + row0);
        ulonglong2 w3 = *(const ulonglong2*)(wb2 + row0 + 4);
        ffma2(a[0], yv.x, w0.x); ffma2(a[1], yv.x, w0.y);
        ffma2(a[2], yv.x, w1.x); ffma2(a[3], yv.x, w1.y);
        ffma2(a[4], yv.x, w2.x); ffma2(a[5], yv.x, w2.y);
        ffma2(a[6], yv.x, w3.x); ffma2(a[7], yv.x, w3.y);
        const int row1 = row0 + 128;
        w0 = *(const ulonglong2*)(wb  + row1);
        w1 = *(const ulonglong2*)(wb  + row1 + 4);
        w2 = *(const ulonglong2*)(wb2 + row1);
        w3 = *(const ulonglong2*)(wb2 + row1 + 4);
        ffma2(a[0], yv.y, w0.x); ffma2(a[1], yv.y, w0.y);
        ffma2(a[2], yv.y, w1.x); ffma2(a[3], yv.y, w1.y);
        ffma2(a[4], yv.y, w2.x); ffma2(a[5], yv.y, w2.y);
        ffma2(a[6], yv.y, w3.x); ffma2(a[7], yv.y, w3.y);
    }
}

template<int K>
__device__ __forceinline__ void layer64s(const float* __restrict__ in, int sIn,
        const float* __restrict__ Wp, const float* __restrict__ bias,
        float* __restrict__ out, int r, int g4)
{
    u64 a[8] = {0, 0, 0, 0, 0, 0, 0, 0};
    gemm64acc<K>(in + r * sIn, Wp, g4, a);
    float* o = out + r * SP64;
    #pragma unroll
    for (int j = 0; j < 4; j++) {
        o[g4 + j]      = hadd2(a[j])     + bias[g4 + j];
        o[32 + g4 + j] = hadd2(a[4 + j]) + bias[32 + g4 + j];
    }
}

__device__ __forceinline__ void decode2(const float* __restrict__ zrow,
        const float* __restrict__ Dp, const float* __restrict__ db,
        float* __restrict__ dst, int g4, bool valid)
{
    u64 a[8] = {0, 0, 0, 0, 0, 0, 0, 0};
    gemm64acc<64>(zrow, Dp, g4, a);
    if (valid) {
        float4 v0 = make_float4(hadd2(a[0]) + db[g4 + 0], hadd2(a[1]) + db[g4 + 1],
                                hadd2(a[2]) + db[g4 + 2], hadd2(a[3]) + db[g4 + 3]);
        float4 v1 = make_float4(hadd2(a[4]) + db[32 + g4 + 0], hadd2(a[5]) + db[32 + g4 + 1],
                                hadd2(a[6]) + db[32 + g4 + 2], hadd2(a[7]) + db[32 + g4 + 3]);
        *(float4*)(dst + g4)      = v0;
        *(float4*)(dst + 32 + g4) = v1;
    }
}

__global__ void __launch_bounds__(THREADS, 1)
ode_kernel(const float* __restrict__ ts,   const float* __restrict__ y0,
           const float* __restrict__ encW, const float* __restrict__ encb,
           const float* __restrict__ W1,   const float* __restrict__ b1,
           const float* __restrict__ W2,   const float* __restrict__ b2,
           const float* __restrict__ W3,   const float* __restrict__ b3,
           const float* __restrict__ decW, const float* __restrict__ decb,
           float* __restrict__ ys, float* __restrict__ zs, int T, int B)
{
    extern __shared__ float sm[];
    float* sZ   = sm;                        // [RROWS][SP64]
    float* sY   = sZ  + KSTRIDE;             // stage input / k6
    float* sH1  = sY  + KSTRIDE;             // [RROWS][SP32]
    float* sH2  = sH1 + RROWS * SP32;
    float* sK1  = sH2 + RROWS * SP32;        // k1..k5 contiguous
    float* sW1p = sK1 + 5 * KSTRIDE;         // [32][64]  packed k-pairs
    float* sW2p = sW1p + 2048;               // [16][64]
    float* sW3p = sW2p + 1024;               // [16][128]
    float* sEp  = sW3p + 2048;               // [32][128]
    float* sDp  = sEp  + 4096;               // [32][128]
    float* sb1  = sDp  + 4096;
    float* sb2  = sb1 + 32;
    float* sb3  = sb2 + 32;
    float* sEb  = sb3 + 64;
    float* sDb  = sEb + 64;
    u64*   sC   = (u64*)(sDb + 64);          // 25 splatted stage coeffs
    u64*   sB   = sC + 25;                   // 6 splatted b-weights

    const int tid = threadIdx.x;
    const int r   = tid >> 3;                // row within CTA (warp-local: warp w -> rows 4w..4w+3)
    const int g4  = (tid & 7) << 2;          // 4-output group
    const int c0  = (tid & 7) << 3;          // 8-col group for combines
    const long long gr = (long long)blockIdx.x * RROWS + r;
    const bool valid = gr < B;
    const int zoff = r * SP64 + c0;

    const float dt = (ts[T - 1] - ts[0]) / (float)(T - 1);

    // ---- prologue: stage packed weights / biases / splatted coeffs ----
    for (int i = tid; i < 2048; i += THREADS) { int kp = i >> 6, j = i & 63;  sW1p[i] = W1[(j >> 1) * 64 + 2 * kp + (j & 1)]; }
    for (int i = tid; i < 1024; i += THREADS) { int kp = i >> 6, j = i & 63;  sW2p[i] = W2[(j >> 1) * 32 + 2 * kp + (j & 1)]; }
    for (int i = tid; i < 2048; i += THREADS) { int kp = i >> 7, j = i & 127; sW3p[i] = W3[(j >> 1) * 32 + 2 * kp + (j & 1)]; }
    for (int i = tid; i < 4096; i += THREADS) { int kp = i >> 7, j = i & 127; sEp[i]  = encW[(j >> 1) * 64 + 2 * kp + (j & 1)]; }
    for (int i = tid; i < 4096; i += THREADS) { int kp = i >> 7, j = i & 127; sDp[i]  = decW[(j >> 1) * 64 + 2 * kp + (j & 1)]; }
    if (tid < 32) { sb1[tid] = b1[tid]; sb2[tid] = b2[tid]; }
    if (tid < 64) { sb3[tid] = b3[tid]; sEb[tid] = encb[tid]; sDb[tid] = decb[tid]; }
    if (tid < 25) sC[tid] = splat2(dt * TSIT_C[tid]);
    if (tid >= 32 && tid < 38) sB[tid - 32] = splat2(dt * TSIT_B[tid - 32]);
    for (int i = tid; i < 5 * KSTRIDE; i += THREADS) sK1[i] = 0.f;  // zero-coeff safety at t=1

    // y0 -> sY (row-owner)
    if (valid) {
        *(float4*)&sY[r * SP64 + c0]     = *(const float4*)&y0[gr * 64 + c0];
        *(float4*)&sY[r * SP64 + c0 + 4] = *(const float4*)&y0[gr * 64 + c0 + 4];
    } else {
        *(float4*)&sY[r * SP64 + c0]     = make_float4(0, 0, 0, 0);
        *(float4*)&sY[r * SP64 + c0 + 4] = make_float4(0, 0, 0, 0);
    }
    __syncthreads();   // only CTA-wide barrier: weights visible to all warps

    // ---- encoder + t=0 emit ----
    layer64s<64>(sY, SP64, sEp, sEb, sZ, r, g4);
    __syncwarp();
    if (valid) {
        float* zrow = zs + (size_t)gr * T * 64;
        *(ulonglong2*)(zrow + c0)     = *(const ulonglong2*)&sZ[zoff];
        *(ulonglong2*)(zrow + c0 + 4) = *(const ulonglong2*)&sZ[zoff + 4];
    }
    decode2(sZ + r * SP64, sDp, sDb, ys + (size_t)gr * T * 64, g4, valid);

    // ---- time loop: everything warp-local, __syncwarp only ----
    #pragma unroll 1
    for (int t = 1; t < T; t++) {
        #pragma unroll 1
        for (int s = 0; s < 6; s++) {
            if (s) {
                const u64* Cs = sC + (s - 1) * 5;
                const u64 q0 = Cs[0], q1 = Cs[1], q2 = Cs[2], q3 = Cs[3], q4 = Cs[4];
                #pragma unroll
                for (int h = 0; h < 2; h++) {
                    const int off = zoff + 4 * h;
                    ulonglong2 zz = *(const ulonglong2*)&sZ[off];
                    u64 zx = zz.x, zy = zz.y;
                    const float* kb = sK1 + off;
                    ulonglong2 kv;
                    kv = *(const ulonglong2*)(kb);               ffma2(zx, q0, kv.x); ffma2(zy, q0, kv.y);
                    kv = *(const ulonglong2*)(kb + KSTRIDE);     ffma2(zx, q1, kv.x); ffma2(zy, q1, kv.y);
                    kv = *(const ulonglong2*)(kb + 2 * KSTRIDE); ffma2(zx, q2, kv.x); ffma2(zy, q2, kv.y);
                    kv = *(const ulonglong2*)(kb + 3 * KSTRIDE); ffma2(zx, q3, kv.x); ffma2(zy, q3, kv.y);
                    kv = *(const ulonglong2*)(kb + 4 * KSTRIDE); ffma2(zx, q4, kv.x); ffma2(zy, q4, kv.y);
                    ulonglong2 o; o.x = zx; o.y = zy;
                    *(ulonglong2*)&sY[off] = o;
                }
                __syncwarp();
            }
            const float* min_ = s ? sY : sZ;
            layerN32p<64>(min_, SP64, sW1p, sb1, sH1, r, g4); __syncwarp();
            layerN32p<32>(sH1, SP32, sW2p, sb2, sH2, r, g4);  __syncwarp();
            float* kout = (s == 5) ? sY : (sK1 + s * KSTRIDE);
            layer64s<32>(sH2, SP32, sW3p, sb3, kout, r, g4);  __syncwarp();
        }

        // ---- 5th-order combine: z += dt * sum b_i k_i ; emit zs[t] ----
        {
            const u64 d0 = sB[0], d1 = sB[1], d2 = sB[2], d3 = sB[3], d4 = sB[4], d5 = sB[5];
            float* zrow = zs + ((size_t)gr * T + t) * 64;
            #pragma unroll
            for (int h = 0; h < 2; h++) {
                const int off = zoff + 4 * h;
                ulonglong2 zz = *(const ulonglong2*)&sZ[off];
                u64 zx = zz.x, zy = zz.y;
                const float* kb = sK1 + off;
                ulonglong2 kv;
                kv = *(const ulonglong2*)(kb);               ffma2(zx, d0, kv.x); ffma2(zy, d0, kv.y);
                kv = *(const ulonglong2*)(kb + KSTRIDE);     ffma2(zx, d1, kv.x); ffma2(zy, d1, kv.y);
                kv = *(const ulonglong2*)(kb + 2 * KSTRIDE); ffma2(zx, d2, kv.x); ffma2(zy, d2, kv.y);
                kv = *(const ulonglong2*)(kb + 3 * KSTRIDE); ffma2(zx, d3, kv.x); ffma2(zy, d3, kv.y);
                kv = *(const ulonglong2*)(kb + 4 * KSTRIDE); ffma2(zx, d4, kv.x); ffma2(zy, d4, kv.y);
                kv = *(const ulonglong2*)&sY[off];           ffma2(zx, d5, kv.x); ffma2(zy, d5, kv.y);
                ulonglong2 o; o.x = zx; o.y = zy;
                *(ulonglong2*)&sZ[off] = o;
                if (valid) *(ulonglong2*)(zrow + c0 + 4 * h) = o;
            }
            __syncwarp();
        }

        decode2(sZ + r * SP64, sDp, sDb, ys + ((size_t)gr * T + t) * 64, g4, valid);
    }
}

extern "C" void kernel_launch(void* const* d_in, const int* in_sizes, int n_in,
                              void* d_out, int out_size)
{
    const float* ts   = (const float*)d_in[0];
    const float* y0   = (const float*)d_in[1];
    const float* encW = (const float*)d_in[2];
    const float* encb = (const float*)d_in[3];
    const float* W1   = (const float*)d_in[4];
    const float* b1   = (const float*)d_in[5];
    const float* W2   = (const float*)d_in[6];
    const float* b2   = (const float*)d_in[7];
    const float* W3   = (const float*)d_in[8];
    const float* b3   = (const float*)d_in[9];
    const float* decW = (const float*)d_in[10];
    const float* decb = (const float*)d_in[11];

    const int T = in_sizes[0];         // 101
    const int B = in_sizes[1] / 64;    // 4096

    float* ys = (float*)d_out;                   // [B, T, 64]
    float* zs = ys + (size_t)B * T * 64;         // [B, T, 64]

    const size_t smem_bytes = (size_t)NF_SMEM * sizeof(float);  // ~113 KB
    cudaFuncSetAttribute(ode_kernel, cudaFuncAttributeMaxDynamicSharedMemorySize,
                         (int)smem_bytes);

    const int blocks = (B + RROWS - 1) / RROWS;  // 147
    ode_kernel<<<blocks, THREADS, smem_bytes>>>(ts, y0, encW, encb, W1, b1, W2, b2,
                                                W3, b3, decW, decb, ys, zs, T, B);
}

// round 11
// speedup vs baseline: 3.2453x; 3.0315x over previous
#include <cuda_runtime.h>

#define THREADS 224
#define RROWS   28
#define SP64    68
#define SP32    36
#define KSTRIDE (RROWS*SP64)

// smem floats: 7 act64 + 2 act32 + sEp + sDp + sEb + 62 (coeff u64s)
#define NF_SMEM (7*KSTRIDE + 2*RROWS*SP32 + 4096 + 4096 + 64 + 62)

typedef unsigned long long u64;

__constant__ float TSIT_C[25] = {
    0.161f, 0.f, 0.f, 0.f, 0.f,
    -0.008480655492356989f, 0.335480655492357f, 0.f, 0.f, 0.f,
    2.8971530571054935f, -6.359448489975075f, 4.3622954328695815f, 0.f, 0.f,
    5.325864828439257f, -11.748883564062828f, 7.4955393428898365f, -0.09249506636175525f, 0.f,
    5.86145544294642f, -12.92096931784711f, 8.159367898576159f, -0.071584973281401f, -0.028269050394068383f
};
__constant__ float TSIT_B[6] = {
    0.09646076681806523f, 0.01f, 0.4798896504144996f,
    1.379008574103742f, -3.290069515436081f, 2.324710524099774f
};

__device__ __forceinline__ void ffma2(u64 &d, u64 a, u64 b) {
    asm("fma.rn.f32x2 %0, %1, %2, %0;" : "+l"(d) : "l"(a), "l"(b));
}
__device__ __forceinline__ float hadd2(u64 a) {
    float lo, hi;
    asm("mov.b64 {%0,%1}, %2;" : "=f"(lo), "=f"(hi) : "l"(a));
    return lo + hi;
}
__device__ __forceinline__ u64 splat2(float c) {
    u64 d; asm("mov.b64 %0, {%1,%1};" : "=l"(d) : "f"(c)); return d;
}
__device__ __forceinline__ float fast_tanh(float x) {
    float e = __expf(2.0f * x);
    return 1.0f - __fdividef(2.0f, e + 1.0f);
}

// ---- encode-only GEMM (smem packed weights, 8 lanes/row x 8 outputs) ----
__device__ __forceinline__ void layer64s_enc(const float* __restrict__ in,
        const float* __restrict__ Wp, const float* __restrict__ bias,
        float* __restrict__ out, int r, int g4)
{
    u64 a[8] = {0,0,0,0,0,0,0,0};
    const float* yrow = in + r * SP64;
    const float* wb  = Wp + 2 * g4;
    const float* wb2 = Wp + 64 + 2 * g4;
    #pragma unroll
    for (int q = 0; q < 16; q++) {
        ulonglong2 yv = *(const ulonglong2*)(yrow + 4 * q);
        const int row0 = 256 * q;
        ulonglong2 w0 = *(const ulonglong2*)(wb  + row0);
        ulonglong2 w1 = *(const ulonglong2*)(wb  + row0 + 4);
        ulonglong2 w2 = *(const ulonglong2*)(wb2 + row0);
        ulonglong2 w3 = *(const ulonglong2*)(wb2 + row0 + 4);
        ffma2(a[0], yv.x, w0.x); ffma2(a[1], yv.x, w0.y);
        ffma2(a[2], yv.x, w1.x); ffma2(a[3], yv.x, w1.y);
        ffma2(a[4], yv.x, w2.x); ffma2(a[5], yv.x, w2.y);
        ffma2(a[6], yv.x, w3.x); ffma2(a[7], yv.x, w3.y);
        const int row1 = row0 + 128;
        w0 = *(const ulonglong2*)(wb  + row1);
        w1 = *(const ulonglong2*)(wb  + row1 + 4);
        w2 = *(const ulonglong2*)(wb2 + row1);
        w3 = *(const ulonglong2*)(wb2 + row1 + 4);
        ffma2(a[0], yv.y, w0.x); ffma2(a[1], yv.y, w0.y);
        ffma2(a[2], yv.y, w1.x); ffma2(a[3], yv.y, w1.y);
        ffma2(a[4], yv.y, w2.x); ffma2(a[5], yv.y, w2.y);
        ffma2(a[6], yv.y, w3.x); ffma2(a[7], yv.y, w3.y);
    }
    float* o = out + r * SP64;
    #pragma unroll
    for (int j = 0; j < 4; j++) {
        o[g4 + j]      = hadd2(a[j])     + bias[g4 + j];
        o[32 + g4 + j] = hadd2(a[4 + j]) + bias[32 + g4 + j];
    }
}

// ---- MLP with register weights: warp = 4 rows, lane = output index ----
__device__ __forceinline__ void mlp_reg(
    const float* __restrict__ yb,          // 64-wide input buffer (CTA base)
    float* __restrict__ sH1, float* __restrict__ sH2,
    float* __restrict__ kout,              // 64-wide output buffer (CTA base)
    const u64* __restrict__ w1, const u64* __restrict__ w2,
    const u64* __restrict__ w3a, const u64* __restrict__ w3b,
    float b1l, float b2l, float b3l, float b3h,
    int rowbase, int lane)
{
    const float* y0 = yb + (rowbase + 0) * SP64;
    const float* y1 = yb + (rowbase + 1) * SP64;
    const float* y2 = yb + (rowbase + 2) * SP64;
    const float* y3 = yb + (rowbase + 3) * SP64;
    // layer 1: 64 -> 32, out[lane]
    {
        u64 a0 = 0, a1 = 0, a2 = 0, a3 = 0;
        #pragma unroll
        for (int q = 0; q < 16; q++) {
            ulonglong2 v0 = *(const ulonglong2*)(y0 + 4 * q);
            ulonglong2 v1 = *(const ulonglong2*)(y1 + 4 * q);
            ulonglong2 v2 = *(const ulonglong2*)(y2 + 4 * q);
            ulonglong2 v3 = *(const ulonglong2*)(y3 + 4 * q);
            const u64 wA = w1[2 * q], wB = w1[2 * q + 1];
            ffma2(a0, v0.x, wA); ffma2(a0, v0.y, wB);
            ffma2(a1, v1.x, wA); ffma2(a1, v1.y, wB);
            ffma2(a2, v2.x, wA); ffma2(a2, v2.y, wB);
            ffma2(a3, v3.x, wA); ffma2(a3, v3.y, wB);
        }
        sH1[(rowbase + 0) * SP32 + lane] = fast_tanh(hadd2(a0) + b1l);
        sH1[(rowbase + 1) * SP32 + lane] = fast_tanh(hadd2(a1) + b1l);
        sH1[(rowbase + 2) * SP32 + lane] = fast_tanh(hadd2(a2) + b1l);
        sH1[(rowbase + 3) * SP32 + lane] = fast_tanh(hadd2(a3) + b1l);
    }
    __syncwarp();
    // layer 2: 32 -> 32
    {
        const float* h0 = sH1 + (rowbase + 0) * SP32;
        const float* h1 = sH1 + (rowbase + 1) * SP32;
        const float* h2 = sH1 + (rowbase + 2) * SP32;
        const float* h3 = sH1 + (rowbase + 3) * SP32;
        u64 a0 = 0, a1 = 0, a2 = 0, a3 = 0;
        #pragma unroll
        for (int q = 0; q < 8; q++) {
            ulonglong2 v0 = *(const ulonglong2*)(h0 + 4 * q);
            ulonglong2 v1 = *(const ulonglong2*)(h1 + 4 * q);
            ulonglong2 v2 = *(const ulonglong2*)(h2 + 4 * q);
            ulonglong2 v3 = *(const ulonglong2*)(h3 + 4 * q);
            const u64 wA = w2[2 * q], wB = w2[2 * q + 1];
            ffma2(a0, v0.x, wA); ffma2(a0, v0.y, wB);
            ffma2(a1, v1.x, wA); ffma2(a1, v1.y, wB);
            ffma2(a2, v2.x, wA); ffma2(a2, v2.y, wB);
            ffma2(a3, v3.x, wA); ffma2(a3, v3.y, wB);
        }
        sH2[(rowbase + 0) * SP32 + lane] = fast_tanh(hadd2(a0) + b2l);
        sH2[(rowbase + 1) * SP32 + lane] = fast_tanh(hadd2(a1) + b2l);
        sH2[(rowbase + 2) * SP32 + lane] = fast_tanh(hadd2(a2) + b2l);
        sH2[(rowbase + 3) * SP32 + lane] = fast_tanh(hadd2(a3) + b2l);
    }
    __syncwarp();
    // layer 3: 32 -> 64, out[lane] and out[lane+32]
    {
        const float* h0 = sH2 + (rowbase + 0) * SP32;
        const float* h1 = sH2 + (rowbase + 1) * SP32;
        const float* h2 = sH2 + (rowbase + 2) * SP32;
        const float* h3 = sH2 + (rowbase + 3) * SP32;
        u64 aA0 = 0, aA1 = 0, aA2 = 0, aA3 = 0;
        u64 aB0 = 0, aB1 = 0, aB2 = 0, aB3 = 0;
        #pragma unroll
        for (int q = 0; q < 8; q++) {
            ulonglong2 v0 = *(const ulonglong2*)(h0 + 4 * q);
            ulonglong2 v1 = *(const ulonglong2*)(h1 + 4 * q);
            ulonglong2 v2 = *(const ulonglong2*)(h2 + 4 * q);
            ulonglong2 v3 = *(const ulonglong2*)(h3 + 4 * q);
            const u64 wa0 = w3a[2 * q], wa1 = w3a[2 * q + 1];
            const u64 wb0 = w3b[2 * q], wb1 = w3b[2 * q + 1];
            ffma2(aA0, v0.x, wa0); ffma2(aA0, v0.y, wa1);
            ffma2(aB0, v0.x, wb0); ffma2(aB0, v0.y, wb1);
            ffma2(aA1, v1.x, wa0); ffma2(aA1, v1.y, wa1);
            ffma2(aB1, v1.x, wb0); ffma2(aB1, v1.y, wb1);
            ffma2(aA2, v2.x, wa0); ffma2(aA2, v2.y, wa1);
            ffma2(aB2, v2.x, wb0); ffma2(aB2, v2.y, wb1);
            ffma2(aA3, v3.x, wa0); ffma2(aA3, v3.y, wa1);
            ffma2(aB3, v3.x, wb0); ffma2(aB3, v3.y, wb1);
        }
        float* o0 = kout + (rowbase + 0) * SP64;
        float* o1 = kout + (rowbase + 1) * SP64;
        float* o2 = kout + (rowbase + 2) * SP64;
        float* o3 = kout + (rowbase + 3) * SP64;
        o0[lane] = hadd2(aA0) + b3l;  o0[32 + lane] = hadd2(aB0) + b3h;
        o1[lane] = hadd2(aA1) + b3l;  o1[32 + lane] = hadd2(aB1) + b3h;
        o2[lane] = hadd2(aA2) + b3l;  o2[32 + lane] = hadd2(aB2) + b3h;
        o3[lane] = hadd2(aA3) + b3l;  o3[32 + lane] = hadd2(aB3) + b3h;
    }
    __syncwarp();
}

// ---- decoder: lane outputs {lane, lane+32}, smem weights amortized over rows ----
__device__ __forceinline__ void decode_reg(
    const float* __restrict__ sZ, const float* __restrict__ Dp,
    float dblo, float dbhi, float* __restrict__ ys,
    long long grow0, int T, int t, int rowbase, int lane, int B)
{
    #pragma unroll
    for (int half = 0; half < 2; half++) {
        const int rb = rowbase + 2 * half;
        const float* z0 = sZ + (rb + 0) * SP64;
        const float* z1 = sZ + (rb + 1) * SP64;
        u64 aA0 = 0, aB0 = 0, aA1 = 0, aB1 = 0;
        #pragma unroll
        for (int q = 0; q < 16; q++) {
            u64 wl0 = *(const u64*)&Dp[(2 * q) * 128 + 2 * lane];
            u64 wh0 = *(const u64*)&Dp[(2 * q) * 128 + 64 + 2 * lane];
            u64 wl1 = *(const u64*)&Dp[(2 * q + 1) * 128 + 2 * lane];
            u64 wh1 = *(const u64*)&Dp[(2 * q + 1) * 128 + 64 + 2 * lane];
            ulonglong2 v0 = *(const ulonglong2*)(z0 + 4 * q);
            ulonglong2 v1 = *(const ulonglong2*)(z1 + 4 * q);
            ffma2(aA0, v0.x, wl0); ffma2(aA0, v0.y, wl1);
            ffma2(aB0, v0.x, wh0); ffma2(aB0, v0.y, wh1);
            ffma2(aA1, v1.x, wl0); ffma2(aA1, v1.y, wl1);
            ffma2(aB1, v1.x, wh0); ffma2(aB1, v1.y, wh1);
        }
        long long g0 = grow0 + 2 * half;
        if (g0 < B) {
            float* d = ys + ((size_t)g0 * T + t) * 64;
            d[lane] = hadd2(aA0) + dblo;  d[32 + lane] = hadd2(aB0) + dbhi;
        }
        if (g0 + 1 < B) {
            float* d = ys + ((size_t)(g0 + 1) * T + t) * 64;
            d[lane] = hadd2(aA1) + dblo;  d[32 + lane] = hadd2(aB1) + dbhi;
        }
    }
}

__global__ void __launch_bounds__(THREADS, 1)
ode_kernel(const float* __restrict__ ts,   const float* __restrict__ y0,
           const float* __restrict__ encW, const float* __restrict__ encb,
           const float* __restrict__ W1,   const float* __restrict__ b1,
           const float* __restrict__ W2,   const float* __restrict__ b2,
           const float* __restrict__ W3,   const float* __restrict__ b3,
           const float* __restrict__ decW, const float* __restrict__ decb,
           float* __restrict__ ys, float* __restrict__ zs, int T, int B)
{
    extern __shared__ float sm[];
    float* sZ   = sm;                        // [RROWS][SP64]
    float* sY   = sZ  + KSTRIDE;
    float* sH1  = sY  + KSTRIDE;             // [RROWS][SP32]
    float* sH2  = sH1 + RROWS * SP32;
    float* sK1  = sH2 + RROWS * SP32;        // k1..k5
    float* sEp  = sK1 + 5 * KSTRIDE;         // [32][128] packed encW
    float* sDp  = sEp + 4096;                // [32][128] packed decW
    float* sEb  = sDp + 4096;                // [64]
    u64*   sC   = (u64*)(sEb + 64);          // 25
    u64*   sB   = sC + 25;                   // 6

    const int tid  = threadIdx.x;
    const int lane = tid & 31;
    const int wrp  = tid >> 5;
    const int rowbase = wrp * 4;
    const int r    = tid >> 3;               // combine/encode mapping (warp-local)
    const int g4   = (tid & 7) << 2;
    const int c0   = (tid & 7) << 3;
    const long long gr = (long long)blockIdx.x * RROWS + r;
    const long long grow0 = (long long)blockIdx.x * RROWS + rowbase;
    const bool valid = gr < B;
    const int zoff = r * SP64 + c0;

    const float dt = (ts[T - 1] - ts[0]) / (float)(T - 1);

    // ---- register weights (per lane: output row `lane`) ----
    u64 w1r[32], w2r[16], w3ar[16], w3br[16];
    #pragma unroll
    for (int p = 0; p < 32; p++) w1r[p] = *(const u64*)&W1[lane * 64 + 2 * p];
    #pragma unroll
    for (int p = 0; p < 16; p++) w2r[p] = *(const u64*)&W2[lane * 32 + 2 * p];
    #pragma unroll
    for (int p = 0; p < 16; p++) {
        w3ar[p] = *(const u64*)&W3[lane * 32 + 2 * p];
        w3br[p] = *(const u64*)&W3[(lane + 32) * 32 + 2 * p];
    }
    const float b1l = b1[lane], b2l = b2[lane];
    const float b3l = b3[lane], b3h = b3[lane + 32];
    const float dblo = decb[lane], dbhi = decb[lane + 32];

    // ---- smem staging: packed enc/dec weights, coeffs, zero k bufs, y0 ----
    for (int i = tid; i < 4096; i += THREADS) { int kp = i >> 7, j = i & 127; sEp[i] = encW[(j >> 1) * 64 + 2 * kp + (j & 1)]; }
    for (int i = tid; i < 4096; i += THREADS) { int kp = i >> 7, j = i & 127; sDp[i] = decW[(j >> 1) * 64 + 2 * kp + (j & 1)]; }
    if (tid < 64) sEb[tid] = encb[tid];
    if (tid < 25) sC[tid] = splat2(dt * TSIT_C[tid]);
    if (tid >= 32 && tid < 38) sB[tid - 32] = splat2(dt * TSIT_B[tid - 32]);
    for (int i = tid; i < 5 * KSTRIDE; i += THREADS) sK1[i] = 0.f;

    if (valid) {
        *(float4*)&sY[r * SP64 + c0]     = *(const float4*)&y0[gr * 64 + c0];
        *(float4*)&sY[r * SP64 + c0 + 4] = *(const float4*)&y0[gr * 64 + c0 + 4];
    } else {
        *(float4*)&sY[r * SP64 + c0]     = make_float4(0, 0, 0, 0);
        *(float4*)&sY[r * SP64 + c0 + 4] = make_float4(0, 0, 0, 0);
    }
    __syncthreads();   // only CTA-wide barrier

    // ---- encode + t=0 emit ----
    layer64s_enc(sY, sEp, sEb, sZ, r, g4);
    __syncwarp();
    if (valid) {
        float* zrow = zs + (size_t)gr * T * 64;
        *(ulonglong2*)(zrow + c0)     = *(const ulonglong2*)&sZ[zoff];
        *(ulonglong2*)(zrow + c0 + 4) = *(const ulonglong2*)&sZ[zoff + 4];
    }
    decode_reg(sZ, sDp, dblo, dbhi, ys, grow0, T, 0, rowbase, lane, B);

    // ---- time loop (warp-local; __syncwarp only) ----
    #pragma unroll 1
    for (int t = 1; t < T; t++) {
        #pragma unroll 1
        for (int s = 0; s < 6; s++) {
            if (s) {
                const u64* Cs = sC + (s - 1) * 5;
                const u64 q0 = Cs[0], q1 = Cs[1], q2 = Cs[2], q3 = Cs[3], q4 = Cs[4];
                #pragma unroll
                for (int h = 0; h < 2; h++) {
                    const int off = zoff + 4 * h;
                    ulonglong2 zz = *(const ulonglong2*)&sZ[off];
                    u64 zx = zz.x, zy = zz.y;
                    const float* kb = sK1 + off;
                    ulonglong2 kv;
                    kv = *(const ulonglong2*)(kb);               ffma2(zx, q0, kv.x); ffma2(zy, q0, kv.y);
                    kv = *(const ulonglong2*)(kb + KSTRIDE);     ffma2(zx, q1, kv.x); ffma2(zy, q1, kv.y);
                    kv = *(const ulonglong2*)(kb + 2 * KSTRIDE); ffma2(zx, q2, kv.x); ffma2(zy, q2, kv.y);
                    kv = *(const ulonglong2*)(kb + 3 * KSTRIDE); ffma2(zx, q3, kv.x); ffma2(zy, q3, kv.y);
                    kv = *(const ulonglong2*)(kb + 4 * KSTRIDE); ffma2(zx, q4, kv.x); ffma2(zy, q4, kv.y);
                    ulonglong2 o; o.x = zx; o.y = zy;
                    *(ulonglong2*)&sY[off] = o;
                }
                __syncwarp();
            }
            const float* yin = s ? sY : sZ;
            float* kout = (s == 5) ? sY : (sK1 + s * KSTRIDE);
            mlp_reg(yin, sH1, sH2, kout, w1r, w2r, w3ar, w3br,
                    b1l, b2l, b3l, b3h, rowbase, lane);
        }

        // ---- 5th-order combine + zs emit ----
        {
            const u64 d0 = sB[0], d1 = sB[1], d2 = sB[2], d3 = sB[3], d4 = sB[4], d5 = sB[5];
            float* zrow = zs + ((size_t)gr * T + t) * 64;
            #pragma unroll
            for (int h = 0; h < 2; h++) {
                const int off = zoff + 4 * h;
                ulonglong2 zz = *(const ulonglong2*)&sZ[off];
                u64 zx = zz.x, zy = zz.y;
                const float* kb = sK1 + off;
                ulonglong2 kv;
                kv = *(const ulonglong2*)(kb);               ffma2(zx, d0, kv.x); ffma2(zy, d0, kv.y);
                kv = *(const ulonglong2*)(kb + KSTRIDE);     ffma2(zx, d1, kv.x); ffma2(zy, d1, kv.y);
                kv = *(const ulonglong2*)(kb + 2 * KSTRIDE); ffma2(zx, d2, kv.x); ffma2(zy, d2, kv.y);
                kv = *(const ulonglong2*)(kb + 3 * KSTRIDE); ffma2(zx, d3, kv.x); ffma2(zy, d3, kv.y);
                kv = *(const ulonglong2*)(kb + 4 * KSTRIDE); ffma2(zx, d4, kv.x); ffma2(zy, d4, kv.y);
                kv = *(const ulonglong2*)&sY[off];           ffma2(zx, d5, kv.x); ffma2(zy, d5, kv.y);
                ulonglong2 o; o.x = zx; o.y = zy;
                *(ulonglong2*)&sZ[off] = o;
                if (valid) *(ulonglong2*)(zrow + c0 + 4 * h) = o;
            }
            __syncwarp();
        }

        decode_reg(sZ, sDp, dblo, dbhi, ys, grow0, T, t, rowbase, lane, B);
    }
}

extern "C" void kernel_launch(void* const* d_in, const int* in_sizes, int n_in,
                              void* d_out, int out_size)
{
    const float* ts   = (const float*)d_in[0];
    const float* y0   = (const float*)d_in[1];
    const float* encW = (const float*)d_in[2];
    const float* encb = (const float*)d_in[3];
    const float* W1   = (const float*)d_in[4];
    const float* b1   = (const float*)d_in[5];
    const float* W2   = (const float*)d_in[6];
    const float* b2   = (const float*)d_in[7];
    const float* W3   = (const float*)d_in[8];
    const float* b3   = (const float*)d_in[9];
    const float* decW = (const float*)d_in[10];
    const float* decb = (const float*)d_in[11];

    const int T = in_sizes[0];         // 101
    const int B = in_sizes[1] / 64;    // 4096

    float* ys = (float*)d_out;                   // [B, T, 64]
    float* zs = ys + (size_t)B * T * 64;         // [B, T, 64]

    const size_t smem_bytes = (size_t)NF_SMEM * sizeof(float);  // ~95 KB
    cudaFuncSetAttribute(ode_kernel, cudaFuncAttributeMaxDynamicSharedMemorySize,
                         (int)smem_bytes);

    const int blocks = (B + RROWS - 1) / RROWS;  // 147
    ode_kernel<<<blocks, THREADS, smem_bytes>>>(ts, y0, encW, encb, W1, b1, W2, b2,
                                                W3, b3, decW, decb, ys, zs, T, B);
}